// round 2
// baseline (speedup 1.0000x reference)
#include <cuda_runtime.h>
#include <cuda_bf16.h>

#define N_NODES 100000
#define N_EDGES 1600000
#define D 128

// ---------------- scratch (device globals; no allocation) ----------------
__device__ int   g_deg[N_NODES];      // degree incl. self loop
__device__ int   g_cursor[N_NODES];   // scatter cursors
__device__ int   g_base[N_NODES + 1]; // CSR row offsets (edges only, no self loop)
__device__ float g_dis[N_NODES];      // deg^{-1/2}
__device__ int   g_src[N_EDGES];      // source node per CSR slot
__device__ float g_h[(size_t)N_NODES * D]; // x @ W^T

// ---------------- packed f32x2 helpers ----------------
__device__ __forceinline__ unsigned long long pk2(float lo, float hi) {
    unsigned long long r;
    asm("mov.b64 %0, {%1, %2};" : "=l"(r) : "f"(lo), "f"(hi));
    return r;
}
__device__ __forceinline__ void unpk2(unsigned long long v, float& lo, float& hi) {
    asm("mov.b64 {%0, %1}, %2;" : "=f"(lo), "=f"(hi) : "l"(v));
}
__device__ __forceinline__ void fma2(unsigned long long& d, unsigned long long a,
                                     unsigned long long b) {
    asm("fma.rn.f32x2 %0, %1, %2, %0;" : "+l"(d) : "l"(a), "l"(b));
}

// ---------------- 1. init ----------------
__global__ void init_kernel() {
    int i = blockIdx.x * blockDim.x + threadIdx.x;
    if (i < N_NODES) {
        g_deg[i] = 1;     // self loop
        g_cursor[i] = 0;
    }
}

// ---------------- 2. degree histogram (edge_index is int32: JAX x64 disabled) --
__global__ void hist_kernel(const int* __restrict__ ei) {
    int e = blockIdx.x * blockDim.x + threadIdx.x;
    if (e < N_EDGES) {
        int col = ei[N_EDGES + e];
        if ((unsigned)col < (unsigned)N_NODES)
            atomicAdd(&g_deg[col], 1);
    }
}

// ---------------- 3. single-block scan: base[], dis[] ----------------
__global__ void scan_kernel() {
    __shared__ int s[1024];
    const int t = threadIdx.x;
    const int chunk = (N_NODES + 1023) / 1024;  // 98
    int start = t * chunk;
    int end = start + chunk; if (end > N_NODES) end = N_NODES;
    if (start > N_NODES) start = N_NODES;

    int sum = 0;
    for (int i = start; i < end; i++) sum += g_deg[i] - 1;
    s[t] = sum;
    __syncthreads();
    // Hillis-Steele inclusive scan
    for (int off = 1; off < 1024; off <<= 1) {
        int v = (t >= off) ? s[t - off] : 0;
        __syncthreads();
        s[t] += v;
        __syncthreads();
    }
    int prefix = (t == 0) ? 0 : s[t - 1];
    for (int i = start; i < end; i++) {
        g_base[i] = prefix;
        int d = g_deg[i];
        prefix += d - 1;
        g_dis[i] = rsqrtf((float)d);
    }
    if (t == 1023) g_base[N_NODES] = s[1023];
}

// ---------------- 4. scatter edges into CSR ----------------
__global__ void scatter_kernel(const int* __restrict__ ei) {
    int e = blockIdx.x * blockDim.x + threadIdx.x;
    if (e < N_EDGES) {
        int row = ei[e];
        int col = ei[N_EDGES + e];
        if ((unsigned)row < (unsigned)N_NODES && (unsigned)col < (unsigned)N_NODES) {
            int pos = g_base[col] + atomicAdd(&g_cursor[col], 1);
            if ((unsigned)pos < (unsigned)N_EDGES)
                g_src[pos] = row;
        }
    }
}

// ---------------- 5. GEMM: h = x @ W^T (fp32, packed f32x2 FMA) ----------------
// Tile 128 rows x 128 cols, K=128 full. 256 threads, 8x8 micro-tile as 8x4 f32x2.
__global__ void gemm_kernel(const float* __restrict__ x, const float* __restrict__ w) {
    extern __shared__ float smem[];
    float* xs = smem;            // [128][128] row-major
    float* wt = smem + D * D;    // wt[k][j] = W[j][k]

    const int tid = threadIdx.x;
    const int row0 = blockIdx.x * 128;

    // load x tile (coalesced float4)
    for (int c = tid; c < 128 * 32; c += 256) {
        int m = c >> 5, k4 = c & 31;
        int row = row0 + m;
        float4 v = make_float4(0.f, 0.f, 0.f, 0.f);
        if (row < N_NODES) v = *(const float4*)&x[(size_t)row * D + k4 * 4];
        *(float4*)&xs[m * D + k4 * 4] = v;
    }
    // load W transposed into smem
    for (int c = tid; c < 128 * 32; c += 256) {
        int j = c & 127, k4 = c >> 7;
        float4 v = *(const float4*)&w[j * D + k4 * 4];
        wt[(k4 * 4 + 0) * D + j] = v.x;
        wt[(k4 * 4 + 1) * D + j] = v.y;
        wt[(k4 * 4 + 2) * D + j] = v.z;
        wt[(k4 * 4 + 3) * D + j] = v.w;
    }
    __syncthreads();

    const int ty = tid >> 4;        // 0..15 -> rows ty*8..+8
    const int tx = tid & 15;        // 0..15 -> cols tx*8..+8
    const int m0 = ty * 8, j0 = tx * 8;

    unsigned long long acc[8][4];
#pragma unroll
    for (int i = 0; i < 8; i++)
#pragma unroll
        for (int j = 0; j < 4; j++) acc[i][j] = 0ull;

#pragma unroll 4
    for (int k = 0; k < 128; k++) {
        float a_[8];
#pragma unroll
        for (int i = 0; i < 8; i++) a_[i] = xs[(m0 + i) * D + k];
        float4 b0 = *(const float4*)&wt[k * D + j0];
        float4 b1 = *(const float4*)&wt[k * D + j0 + 4];
        unsigned long long bp[4];
        bp[0] = pk2(b0.x, b0.y); bp[1] = pk2(b0.z, b0.w);
        bp[2] = pk2(b1.x, b1.y); bp[3] = pk2(b1.z, b1.w);
#pragma unroll
        for (int i = 0; i < 8; i++) {
            unsigned long long ap = pk2(a_[i], a_[i]);
#pragma unroll
            for (int j = 0; j < 4; j++) fma2(acc[i][j], ap, bp[j]);
        }
    }

#pragma unroll
    for (int i = 0; i < 8; i++) {
        int row = row0 + m0 + i;
        if (row < N_NODES) {
            float4 r0, r1;
            unpk2(acc[i][0], r0.x, r0.y); unpk2(acc[i][1], r0.z, r0.w);
            unpk2(acc[i][2], r1.x, r1.y); unpk2(acc[i][3], r1.z, r1.w);
            *(float4*)&g_h[(size_t)row * D + j0] = r0;
            *(float4*)&g_h[(size_t)row * D + j0 + 4] = r1;
        }
    }
}

// ---------------- 6. aggregation: one warp per node, no float atomics ----------
__global__ void agg_kernel(const float* __restrict__ bias, float* __restrict__ out) {
    int warp = (blockIdx.x * blockDim.x + threadIdx.x) >> 5;
    int lane = threadIdx.x & 31;
    if (warp >= N_NODES) return;
    const int n = warp;

    const float dn = g_dis[n];
    // self-loop contribution: h[n] * dn*dn
    float4 acc = *(const float4*)&g_h[(size_t)n * D + lane * 4];
    float sl = dn * dn;
    acc.x *= sl; acc.y *= sl; acc.z *= sl; acc.w *= sl;

    const int s = g_base[n];
    const int e = g_base[n + 1];
    for (int idx = s; idx < e; idx++) {
        int r = g_src[idx];
        float sc = g_dis[r] * dn;
        float4 hv = *(const float4*)&g_h[(size_t)r * D + lane * 4];
        acc.x = fmaf(hv.x, sc, acc.x);
        acc.y = fmaf(hv.y, sc, acc.y);
        acc.z = fmaf(hv.z, sc, acc.z);
        acc.w = fmaf(hv.w, sc, acc.w);
    }

    float4 bb = *(const float4*)&bias[lane * 4];
    acc.x = fmaxf(acc.x + bb.x, 0.f);
    acc.y = fmaxf(acc.y + bb.y, 0.f);
    acc.z = fmaxf(acc.z + bb.z, 0.f);
    acc.w = fmaxf(acc.w + bb.w, 0.f);
    *(float4*)&out[(size_t)n * D + lane * 4] = acc;
}

// ---------------- launch ----------------
extern "C" void kernel_launch(void* const* d_in, const int* in_sizes, int n_in,
                              void* d_out, int out_size) {
    const float* x    = (const float*)d_in[0];
    const int*   ei   = (const int*)d_in[1];     // int32: JAX default x64-disabled
    const float* w    = (const float*)d_in[2];
    const float* bias = (const float*)d_in[3];
    float*       out  = (float*)d_out;

    cudaFuncSetAttribute(gemm_kernel, cudaFuncAttributeMaxDynamicSharedMemorySize,
                         2 * D * D * (int)sizeof(float));

    init_kernel<<<(N_NODES + 255) / 256, 256>>>();
    hist_kernel<<<(N_EDGES + 255) / 256, 256>>>(ei);
    scan_kernel<<<1, 1024>>>();
    scatter_kernel<<<(N_EDGES + 255) / 256, 256>>>(ei);
    gemm_kernel<<<(N_NODES + 127) / 128, 256, 2 * D * D * sizeof(float)>>>(x, w);
    agg_kernel<<<(N_NODES * 32 + 255) / 256, 256>>>(bias, out);
}